// round 13
// baseline (speedup 1.0000x reference)
#include <cuda_runtime.h>

// CostVolumeBidirectional: f1,f2 (8,96,96,320) f32 -> out (8,9,96,320) f32
// out[b][d][h][w] = (1/96) * sum_c f1[b][c][h][w] * f2[b][c][h][w-(d-4)]
// zero where w-(d-4) outside [0,320).
//
// R13: R10 structure (4-col tile, CHUNKS=2, 128-thr blocks, register a/m
// loads) + warp-private smem halo ring. R10's floor was L1tex global
// wavefronts (18/warp-round, 10 of them redundant l/r halo reads); R12's
// SHFL fix added serialized latency. Here each warp STS's its m into a
// private 34-slot ping-pong buffer and reads l/r back via conflict-free
// LDS.128 (smem crossbar, off the global path). Only lanes 0/31 do a
// guarded edge LDG. One __syncwarp per channel; no block-wide syncs in
// the loop. Global wavefronts 18 -> 10 per warp-round.

#define BS 8
#define FS 96
#define H  96
#define W  320
#define WQ (W / 4)      // 80 float4 groups per row
#define NP 9            // disparity planes

#define GROUPS 64       // float4-groups per block
#define CHUNKS 2        // channel chunks per group
#define CHP (FS / CHUNKS)  // 48 channels per thread
#define BLOCK (GROUPS * CHUNKS)   // 128 threads
#define WARPS (BLOCK / 32)        // 4

__global__ __launch_bounds__(BLOCK, 8)
void cost_volume_kernel(const float* __restrict__ f1,
                        const float* __restrict__ f2,
                        float* __restrict__ out) {
    // halo ring (loop) unioned with reduction buffer (epilogue only)
    __shared__ union SmemU {
        float4 halo[WARPS][2][34];         // [warp][pingpong][l,32 m's,r] 4.25KB
        float4 red[CHUNKS][GROUPS][NP];    // 18KB
    } sm;

    const int tid  = threadIdx.x;
    const int g    = tid & (GROUPS - 1);
    const int cc   = tid >> 6;
    const int wid  = tid >> 5;
    const int lane = tid & 31;

    const int t  = blockIdx.x * GROUPS + g;    // global float4-group id
    const int wq = t % WQ;
    const int bh = t / WQ;
    const int h  = bh % H;
    const int b  = bh / H;

    float acc[NP][4];
#pragma unroll
    for (int d = 0; d < NP; d++)
#pragma unroll
        for (int k = 0; k < 4; k++) acc[d][k] = 0.0f;

    const int cs = H * W;
    const size_t base = ((size_t)b * FS + cc * CHP) * cs + (size_t)h * W + (size_t)wq * 4;
    const float* p1 = f1 + base;
    const float* p2 = f2 + base;

    const bool hasL = (wq > 0);
    const bool hasR = (wq < WQ - 1);
    const float4 z4 = make_float4(0.f, 0.f, 0.f, 0.f);

    float4* hb0 = sm.halo[wid][0];
    float4* hb1 = sm.halo[wid][1];

#pragma unroll 2
    for (int c = 0; c < CHP; c++) {
        float4* hb = (c & 1) ? hb1 : hb0;
        const float* q1 = p1 + (size_t)c * cs;
        const float* q2 = p2 + (size_t)c * cs;

        float4 a = *(const float4*)(q1);
        float4 m = *(const float4*)(q2);

        // warp-edge halos: guarded global loads straight into the ring ends
        if (lane == 0)  hb[0]  = hasL ? *(const float4*)(q2 - 4) : z4;
        if (lane == 31) hb[33] = hasR ? *(const float4*)(q2 + 4) : z4;
        hb[lane + 1] = m;
        __syncwarp();

        // interior halos from neighbor lanes' slots; row-boundary lanes
        // (wq==0 / wq==WQ-1 mid-warp) masked to zero exactly as before
        float4 l = hasL ? hb[lane]     : z4;
        float4 r = hasR ? hb[lane + 2] : z4;

        float w12[12] = {l.x, l.y, l.z, l.w,
                         m.x, m.y, m.z, m.w,
                         r.x, r.y, r.z, r.w};
        float av[4] = {a.x, a.y, a.z, a.w};

        // plane d => shift i = d-4; f2 window index = k + 8 - d
#pragma unroll
        for (int d = 0; d < NP; d++) {
#pragma unroll
            for (int k = 0; k < 4; k++) {
                acc[d][k] = fmaf(av[k], w12[k + 8 - d], acc[d][k]);
            }
        }
    }

    // epilogue: partials -> smem (red aliases halo; all halo reads are done),
    // then 2-way reduce + store
    __syncthreads();
#pragma unroll
    for (int d = 0; d < NP; d++) {
        sm.red[cc][g][d] = make_float4(acc[d][0], acc[d][1], acc[d][2], acc[d][3]);
    }
    __syncthreads();

    const float inv = 1.0f / (float)FS;
    for (int item = tid; item < GROUPS * NP; item += BLOCK) {
        const int g2 = item / NP;
        const int d  = item % NP;

        float4 a0 = sm.red[0][g2][d];
        float4 a1 = sm.red[1][g2][d];

        float4 o;
        o.x = (a0.x + a1.x) * inv;
        o.y = (a0.y + a1.y) * inv;
        o.z = (a0.z + a1.z) * inv;
        o.w = (a0.w + a1.w) * inv;

        const int t2  = blockIdx.x * GROUPS + g2;
        const int wq2 = t2 % WQ;
        const int bh2 = t2 / WQ;
        const int h2  = bh2 % H;
        const int b2  = bh2 / H;

        const size_t oidx = (((size_t)b2 * NP + d) * H + h2) * W + (size_t)wq2 * 4;
        *(float4*)(out + oidx) = o;
    }
}

extern "C" void kernel_launch(void* const* d_in, const int* in_sizes, int n_in,
                              void* d_out, int out_size) {
    const float* f1 = (const float*)d_in[0];
    const float* f2 = (const float*)d_in[1];
    float* out = (float*)d_out;

    const int total_groups = BS * H * WQ;          // 61440
    const int grid = total_groups / GROUPS;        // 960 blocks
    cost_volume_kernel<<<grid, BLOCK>>>(f1, f2, out);
}

// round 14
// speedup vs baseline: 1.1405x; 1.1405x over previous
#include <cuda_runtime.h>
#include <cstdint>

// CostVolumeBidirectional: f1,f2 (8,96,96,320) f32 -> out (8,9,96,320) f32
// out[b][d][h][w] = (1/96) * sum_c f1[b][c][h][w] * f2[b][c][h][w-(d-4)]
// zero where w-(d-4) outside [0,320).
//
// R14: warp-private cp.async pipeline (DEPTH=6). R10 is DRAM-latency-bound
// with register-capped MLP (~65KB/SM in flight at 64 regs); R11 proved smem
// staging works but was killed by per-channel __syncthreads; R12/R13 put the
// halo transport on the load's dependency chain. Here each WARP streams its
// f1/f2 channel slices 6 stages ahead via cp.async.cg into warp-private smem
// rings (no registers consumed, ~190KB/SM in flight), computes from
// conflict-free LDS.128, and never block-syncs inside the loop. Halo slots
// come from lanes 0/31 cp.asyncs with zfill at row edges; mid-warp row
// boundaries stay masked per-lane by hasL/hasR.

#define BS 8
#define FS 96
#define H  96
#define W  320
#define WQ (W / 4)      // 80 float4 groups per row
#define NP 9            // disparity planes

#define GROUPS 64       // float4-groups per block
#define CHUNKS 2        // channel chunks per group
#define CHP (FS / CHUNKS)  // 48 channels per thread
#define BLOCK (GROUPS * CHUNKS)   // 128 threads
#define WARPS (BLOCK / 32)        // 4
#define DEPTH 6         // pipeline stages (48 % 6 == 0)

struct __align__(16) Pipe {
    float4 f2h[WARPS][DEPTH][34];   // [l, 32 m's, r] per warp-stage  13,056 B
    float4 f1s[WARPS][DEPTH][32];   //                               12,288 B
};
union SmemU {
    Pipe pipe;                      // 25,344 B (loop)
    float4 red[CHUNKS][GROUPS][NP]; // 18,432 B (epilogue)
};

__device__ __forceinline__ void cp_async16(uint32_t dst, const void* src, int src_size) {
    asm volatile("cp.async.cg.shared.global [%0], [%1], 16, %2;\n"
                 :: "r"(dst), "l"(src), "r"(src_size));
}
__device__ __forceinline__ void cp_commit() {
    asm volatile("cp.async.commit_group;\n" ::: "memory");
}
__device__ __forceinline__ void cp_wait_5() {
    asm volatile("cp.async.wait_group 5;\n" ::: "memory");
}
__device__ __forceinline__ void cp_wait_0() {
    asm volatile("cp.async.wait_group 0;\n" ::: "memory");
}

__global__ __launch_bounds__(BLOCK, 8)
void cost_volume_kernel(const float* __restrict__ f1,
                        const float* __restrict__ f2,
                        float* __restrict__ out) {
    __shared__ SmemU sm;

    const int tid  = threadIdx.x;
    const int g    = tid & (GROUPS - 1);
    const int cc   = tid >> 6;
    const int wid  = tid >> 5;
    const int lane = tid & 31;

    const int t  = blockIdx.x * GROUPS + g;    // global float4-group id
    const int wq = t % WQ;
    const int bh = t / WQ;
    const int h  = bh % H;
    const int b  = bh / H;

    const int cs = H * W;
    const size_t base = ((size_t)b * FS + cc * CHP) * cs + (size_t)h * W + (size_t)wq * 4;
    const float* p1 = f1 + base;
    const float* p2 = f2 + base;

    const bool hasL = (wq > 0);
    const bool hasR = (wq < WQ - 1);
    const float4 z4 = make_float4(0.f, 0.f, 0.f, 0.f);

    const uint32_t s_f2 = (uint32_t)__cvta_generic_to_shared(&sm.pipe.f2h[wid][0][0]);
    const uint32_t s_f1 = (uint32_t)__cvta_generic_to_shared(&sm.pipe.f1s[wid][0][0]);

    // issue one channel's slices into this warp's pipeline slot
    auto issue = [&](int ch, int slot) {
        const float* q1 = p1 + (size_t)ch * cs;
        const float* q2 = p2 + (size_t)ch * cs;
        cp_async16(s_f1 + (slot * 32 + lane) * 16, q1, 16);
        cp_async16(s_f2 + (slot * 34 + lane + 1) * 16, q2, 16);
        if (lane == 0)
            cp_async16(s_f2 + (slot * 34) * 16, hasL ? (q2 - 4) : q2, hasL ? 16 : 0);
        if (lane == 31)
            cp_async16(s_f2 + (slot * 34 + 33) * 16, hasR ? (q2 + 4) : q2, hasR ? 16 : 0);
    };

    // prologue: fill the pipeline (6 committed groups)
#pragma unroll
    for (int s0 = 0; s0 < DEPTH; s0++) {
        issue(s0, s0);
        cp_commit();
    }

    float acc[NP][4];
#pragma unroll
    for (int d = 0; d < NP; d++)
#pragma unroll
        for (int k = 0; k < 4; k++) acc[d][k] = 0.0f;

#pragma unroll 3
    for (int c = 0; c < CHP; c++) {
        const int slot = c % DEPTH;

        cp_wait_5();       // own warp's oldest stage landed
        __syncwarp();      // publish across lanes of this warp

        const float4* f2s = &sm.pipe.f2h[wid][slot][0];
        float4 a = sm.pipe.f1s[wid][slot][lane];
        float4 m = f2s[lane + 1];
        float4 l = hasL ? f2s[lane] : z4;
        float4 r = hasR ? f2s[lane + 2] : z4;

        float w12[12] = {l.x, l.y, l.z, l.w,
                         m.x, m.y, m.z, m.w,
                         r.x, r.y, r.z, r.w};
        float av[4] = {a.x, a.y, a.z, a.w};

        // plane d => shift i = d-4; f2 window index = k + 8 - d
#pragma unroll
        for (int d = 0; d < NP; d++) {
#pragma unroll
            for (int k = 0; k < 4; k++) {
                acc[d][k] = fmaf(av[k], w12[k + 8 - d], acc[d][k]);
            }
        }

        __syncwarp();      // all lanes consumed this slot before reissue
        if (c + DEPTH < CHP) issue(c + DEPTH, slot);
        cp_commit();       // one group per iter keeps wait_group aligned
    }

    // epilogue: drain async copies, then partials -> smem (red aliases pipe),
    // 2-way reduce + store
    cp_wait_0();
    __syncthreads();
#pragma unroll
    for (int d = 0; d < NP; d++) {
        sm.red[cc][g][d] = make_float4(acc[d][0], acc[d][1], acc[d][2], acc[d][3]);
    }
    __syncthreads();

    const float inv = 1.0f / (float)FS;
    for (int item = tid; item < GROUPS * NP; item += BLOCK) {
        const int g2 = item / NP;
        const int d  = item % NP;

        float4 a0 = sm.red[0][g2][d];
        float4 a1 = sm.red[1][g2][d];

        float4 o;
        o.x = (a0.x + a1.x) * inv;
        o.y = (a0.y + a1.y) * inv;
        o.z = (a0.z + a1.z) * inv;
        o.w = (a0.w + a1.w) * inv;

        const int t2  = blockIdx.x * GROUPS + g2;
        const int wq2 = t2 % WQ;
        const int bh2 = t2 / WQ;
        const int h2  = bh2 % H;
        const int b2  = bh2 / H;

        const size_t oidx = (((size_t)b2 * NP + d) * H + h2) * W + (size_t)wq2 * 4;
        *(float4*)(out + oidx) = o;
    }
}

extern "C" void kernel_launch(void* const* d_in, const int* in_sizes, int n_in,
                              void* d_out, int out_size) {
    const float* f1 = (const float*)d_in[0];
    const float* f2 = (const float*)d_in[1];
    float* out = (float*)d_out;

    const int total_groups = BS * H * WQ;          // 61440
    const int grid = total_groups / GROUPS;        // 960 blocks
    cost_volume_kernel<<<grid, BLOCK>>>(f1, f2, out);
}